// round 11
// baseline (speedup 1.0000x reference)
#include <cuda_runtime.h>
#include <cuda_fp16.h>
#include <cstdint>
#include <cstddef>

#define NMAX 100000
#define EMAX 1600000
#define D 128

// ---------------- static device scratch ----------------
__device__ __half g_H[(size_t)NMAX * D];    // ping buffer, fp16
__device__ __half g_A[(size_t)NMAX * D];    // pong buffer, fp16
__device__ int    g_cnt[NMAX];
__device__ float  g_dis[NMAX];
__device__ int    g_rs[NMAX + 1];
__device__ int    g_cur[NMAX];
__device__ int    g_bsum[256];
__device__ int    g_csrs[EMAX];
__device__ float  g_csrw[EMAX];
__device__ float  g_Wt[128 * 128];          // W0*W1
__device__ float  g_W012[128 * 128];        // W0*W1*W2
__device__ float  g_c1[128];                // b0*W1*W2
__device__ float  g_c2[128];                // b1*W2
__device__ float  g_u1[NMAX];               // A*1
__device__ float  g_u2[NMAX];               // A^2*1

// ---------------- graph preprocessing ----------------
__global__ void k_zero(int n) {
    int i = blockIdx.x * blockDim.x + threadIdx.x;
    if (i < n) g_cnt[i] = 0;
}

__global__ void k_count(const int* __restrict__ dst, int e) {
    int i = blockIdx.x * blockDim.x + threadIdx.x;
    if (i < e) atomicAdd(&g_cnt[dst[i]], 1);
}

__global__ void k_scan1(int n) {
    __shared__ int sm[1024];
    int i = blockIdx.x * 1024 + threadIdx.x;
    int v = (i < n) ? g_cnt[i] : 0;
    sm[threadIdx.x] = v;
    __syncthreads();
    for (int off = 1; off < 1024; off <<= 1) {
        int t = (threadIdx.x >= (unsigned)off) ? sm[threadIdx.x - off] : 0;
        __syncthreads();
        sm[threadIdx.x] += t;
        __syncthreads();
    }
    if (i < n) g_rs[i] = sm[threadIdx.x] - v;   // exclusive within block
    if (threadIdx.x == 1023) g_bsum[blockIdx.x] = sm[1023];
}

__global__ void k_scan3(int n, int e) {
    __shared__ int red[128];
    int b = blockIdx.x;
    int t = threadIdx.x;
    if (t < 128) red[t] = (t < b) ? g_bsum[t] : 0;
    __syncthreads();
    for (int off = 64; off > 0; off >>= 1) {
        if (t < (unsigned)off) red[t] += red[t + off];
        __syncthreads();
    }
    int pre = red[0];
    int i = b * 1024 + t;
    if (i < n) {
        int v = g_rs[i] + pre;
        g_rs[i] = v;
        g_cur[i] = v;
        g_dis[i] = rsqrtf((float)(g_cnt[i] + 1));   // +1 self loop
    }
    if (i == 0) g_rs[n] = e;
}

__global__ void k_scatter(const int* __restrict__ src, const int* __restrict__ dst, int e) {
    int i = blockIdx.x * blockDim.x + threadIdx.x;
    if (i < e) {
        int s = src[i], d = dst[i];
        int p = atomicAdd(&g_cur[d], 1);
        g_csrs[p] = s;
        g_csrw[p] = g_dis[s] * g_dis[d];
    }
}

// ---------------- tiny fp32 matmul: C[128x128] = A*B ----------------
__global__ void k_mm128(const float* __restrict__ A, const float* __restrict__ B,
                        float* __restrict__ C) {
    int id = blockIdx.x * 256 + threadIdx.x;
    int r = id >> 7, c = id & 127;
    float s = 0.0f;
#pragma unroll 8
    for (int k = 0; k < 128; k++) s = fmaf(A[r * 128 + k], B[k * 128 + c], s);
    C[id] = s;
}

// ---------------- bias correction vectors: c1 = b0*W1*W2, c2 = b1*W2 ----------------
__global__ void k_cvec(const float* __restrict__ b0, const float* __restrict__ b1,
                       const float* __restrict__ W1, const float* __restrict__ W2) {
    __shared__ float t1[128];
    int j = threadIdx.x;
    float s = 0.0f;
    for (int k = 0; k < 128; k++) s = fmaf(b0[k], W1[k * 128 + j], s);
    t1[j] = s;
    __syncthreads();
    float s1 = 0.0f, s2 = 0.0f;
    for (int k = 0; k < 128; k++) {
        float w = W2[k * 128 + j];
        s1 = fmaf(t1[k], w, s1);
        s2 = fmaf(b1[k], w, s2);
    }
    g_c1[j] = s1;
    g_c2[j] = s2;
}

// ---------------- scalar aggregations: u1 = A*1, u2 = A*u1 ----------------
__global__ void k_aggs1(int n) {
    int v = blockIdx.x * blockDim.x + threadIdx.x;
    if (v >= n) return;
    float dv = g_dis[v];
    float s = dv * dv;
    int end = g_rs[v + 1];
    for (int e = g_rs[v]; e < end; e++) s += g_csrw[e];
    g_u1[v] = s;
}

__global__ void k_aggs2(int n) {
    int v = blockIdx.x * blockDim.x + threadIdx.x;
    if (v >= n) return;
    float dv = g_dis[v];
    float s = dv * dv * g_u1[v];
    int end = g_rs[v + 1];
    for (int e = g_rs[v]; e < end; e++) s += g_csrw[e] * g_u1[g_csrs[e]];
    g_u2[v] = s;
}

// ---------------- MMA helpers ----------------
__device__ __forceinline__ void mma_f16(float* c, const unsigned* a, unsigned b0, unsigned b1) {
    asm volatile(
        "mma.sync.aligned.m16n8k16.row.col.f32.f16.f16.f32 "
        "{%0,%1,%2,%3}, {%4,%5,%6,%7}, {%8,%9}, {%0,%1,%2,%3};\n"
        : "+f"(c[0]), "+f"(c[1]), "+f"(c[2]), "+f"(c[3])
        : "r"(a[0]), "r"(a[1]), "r"(a[2]), "r"(a[3]), "r"(b0), "r"(b1));
}

#define BSTR 136   // smem stride in uint32 -> conflict-free frag loads

// ---------------- GEMM: Y = X(fp32 -> fp16) @ W012, single pass ----------------
__global__ void __launch_bounds__(256)
k_gemm(const float* __restrict__ X, const float* __restrict__ W,
       __half* __restrict__ H, int n) {
    __shared__ unsigned Bh[64 * BSTR];

    int tid = threadIdx.x;
    for (int i = tid; i < 64 * 128; i += 256) {
        int j = i >> 7, c = i & 127;
        float w0 = W[(2 * j) * 128 + c];
        float w1 = W[(2 * j + 1) * 128 + c];
        __half2 h = __floats2half2_rn(w0, w1);
        Bh[j * BSTR + c] = *(unsigned*)&h;
    }
    __syncthreads();

    int wid = tid >> 5, lane = tid & 31;
    int warp_m = wid >> 1, warp_n = wid & 1;
    int g = lane >> 2, tg = lane & 3;
    int rbase = blockIdx.x * 128 + warp_m * 32;
    int cbase = warp_n * 64;
    int nclamp = n - 1;

    float acc[2][8][4];
#pragma unroll
    for (int mf = 0; mf < 2; mf++)
#pragma unroll
        for (int nt = 0; nt < 8; nt++)
#pragma unroll
            for (int q = 0; q < 4; q++) acc[mf][nt][q] = 0.0f;

    for (int k0 = 0; k0 < 128; k0 += 16) {
        unsigned a[2][4];
#pragma unroll
        for (int mf = 0; mf < 2; mf++) {
            int r0 = rbase + mf * 16 + g;
            int r1 = r0 + 8;
            if (r0 > nclamp) r0 = nclamp;
            if (r1 > nclamp) r1 = nclamp;
            const float* p0 = X + (size_t)r0 * D + k0 + 2 * tg;
            const float* p1 = X + (size_t)r1 * D + k0 + 2 * tg;
            float2 f00 = *(const float2*)(p0);
            float2 f01 = *(const float2*)(p0 + 8);
            float2 f10 = *(const float2*)(p1);
            float2 f11 = *(const float2*)(p1 + 8);
            __half2 h0 = __floats2half2_rn(f00.x, f00.y);
            __half2 h1 = __floats2half2_rn(f10.x, f10.y);
            __half2 h2 = __floats2half2_rn(f01.x, f01.y);
            __half2 h3 = __floats2half2_rn(f11.x, f11.y);
            a[mf][0] = *(unsigned*)&h0;
            a[mf][1] = *(unsigned*)&h1;
            a[mf][2] = *(unsigned*)&h2;
            a[mf][3] = *(unsigned*)&h3;
        }
#pragma unroll
        for (int nt = 0; nt < 8; nt++) {
            int c = cbase + nt * 8 + g;
            int i0 = (k0 / 2 + tg) * BSTR + c;
            int i1 = i0 + 4 * BSTR;
            unsigned b0 = Bh[i0], b1 = Bh[i1];
#pragma unroll
            for (int mf = 0; mf < 2; mf++)
                mma_f16(acc[mf][nt], a[mf], b0, b1);
        }
    }

#pragma unroll
    for (int mf = 0; mf < 2; mf++) {
        int r0 = rbase + mf * 16 + g;
        int r1 = r0 + 8;
#pragma unroll
        for (int nt = 0; nt < 8; nt++) {
            int c = cbase + nt * 8 + 2 * tg;
            if (r0 < n) {
                __half2 v = __floats2half2_rn(acc[mf][nt][0], acc[mf][nt][1]);
                *(__half2*)(H + (size_t)r0 * D + c) = v;
            }
            if (r1 < n) {
                __half2 v = __floats2half2_rn(acc[mf][nt][2], acc[mf][nt][3]);
                *(__half2*)(H + (size_t)r1 * D + c) = v;
            }
        }
    }
}

// ---------------- aggregation v2: uint4 loads, two edges per warp step ----------------
// lane = half*16 + c16; each lane owns 8 columns (c16*8 .. c16*8+7).
// half 0 processes even edges, half 1 odd edges; cross-half shfl reduce at end.
__device__ __forceinline__ void unpack_fma8(float* acc, uint4 u, float w) {
    float2 p0 = __half22float2(*(__half2*)&u.x);
    float2 p1 = __half22float2(*(__half2*)&u.y);
    float2 p2 = __half22float2(*(__half2*)&u.z);
    float2 p3 = __half22float2(*(__half2*)&u.w);
    acc[0] = fmaf(w, p0.x, acc[0]); acc[1] = fmaf(w, p0.y, acc[1]);
    acc[2] = fmaf(w, p1.x, acc[2]); acc[3] = fmaf(w, p1.y, acc[3]);
    acc[4] = fmaf(w, p2.x, acc[4]); acc[5] = fmaf(w, p2.y, acc[5]);
    acc[6] = fmaf(w, p3.x, acc[6]); acc[7] = fmaf(w, p3.y, acc[7]);
}

__device__ __forceinline__ void agg_core2(const uint4* __restrict__ H4, int node,
                                          int half, int c16, float* acc) {
#pragma unroll
    for (int i = 0; i < 8; i++) acc[i] = 0.0f;

    // self term (half 0 only)
    {
        float dv = g_dis[node];
        uint4 uv = H4[(size_t)node * 16 + c16];
        float selfw = (half == 0) ? dv * dv : 0.0f;
        unpack_fma8(acc, uv, selfw);
    }

    int e = g_rs[node], end = g_rs[node + 1];
    // main: 8 edges per iter (4 per half-warp) -> 4 outstanding LDG.128 per lane
    for (; e + 8 <= end; e += 8) {
        int i0 = e + half, i1 = e + 2 + half, i2 = e + 4 + half, i3 = e + 6 + half;
        int   s0 = g_csrs[i0], s1 = g_csrs[i1], s2 = g_csrs[i2], s3 = g_csrs[i3];
        float w0 = g_csrw[i0], w1 = g_csrw[i1], w2 = g_csrw[i2], w3 = g_csrw[i3];
        uint4 u0 = H4[(size_t)s0 * 16 + c16];
        uint4 u1 = H4[(size_t)s1 * 16 + c16];
        uint4 u2 = H4[(size_t)s2 * 16 + c16];
        uint4 u3 = H4[(size_t)s3 * 16 + c16];
        unpack_fma8(acc, u0, w0);
        unpack_fma8(acc, u1, w1);
        unpack_fma8(acc, u2, w2);
        unpack_fma8(acc, u3, w3);
    }
    // tail: 2 edges per iter, guarded
    for (; e < end; e += 2) {
        int idx = e + half;
        if (idx < end) {
            int s = g_csrs[idx];
            float w = g_csrw[idx];
            uint4 u = H4[(size_t)s * 16 + c16];
            unpack_fma8(acc, u, w);
        }
    }
    // combine the two half-warps (same columns, disjoint edges)
#pragma unroll
    for (int i = 0; i < 8; i++)
        acc[i] += __shfl_xor_sync(0xffffffffu, acc[i], 16);
}

// mid aggregation: fp16 -> fp16
__global__ void k_agg_mid(const __half* __restrict__ Hh, __half* __restrict__ Oh, int n) {
    int warp = (blockIdx.x * blockDim.x + threadIdx.x) >> 5;
    int lane = threadIdx.x & 31;
    if (warp >= n) return;
    int half = lane >> 4, c16 = lane & 15;

    float acc[8];
    agg_core2((const uint4*)Hh, warp, half, c16, acc);

    if (half == 0) {
        __half2 h0 = __floats2half2_rn(acc[0], acc[1]);
        __half2 h1 = __floats2half2_rn(acc[2], acc[3]);
        __half2 h2 = __floats2half2_rn(acc[4], acc[5]);
        __half2 h3 = __floats2half2_rn(acc[6], acc[7]);
        uint4 o;
        o.x = *(unsigned*)&h0;
        o.y = *(unsigned*)&h1;
        o.z = *(unsigned*)&h2;
        o.w = *(unsigned*)&h3;
        ((uint4*)Oh)[(size_t)warp * 16 + c16] = o;
    }
}

// final aggregation: + rank-1 bias corrections + b2, fp32 out
__global__ void k_agg_fin(const __half* __restrict__ Hh, const float* __restrict__ b2,
                          float* __restrict__ out, int n) {
    int warp = (blockIdx.x * blockDim.x + threadIdx.x) >> 5;
    int lane = threadIdx.x & 31;
    if (warp >= n) return;
    int half = lane >> 4, c16 = lane & 15;

    float acc[8];
    agg_core2((const uint4*)Hh, warp, half, c16, acc);

    if (half == 0) {
        float u2v = g_u2[warp];
        float u1v = g_u1[warp];
        float4 c1a = ((const float4*)g_c1)[c16 * 2];
        float4 c1b = ((const float4*)g_c1)[c16 * 2 + 1];
        float4 c2a = ((const float4*)g_c2)[c16 * 2];
        float4 c2b = ((const float4*)g_c2)[c16 * 2 + 1];
        float4 ba  = ((const float4*)b2)[c16 * 2];
        float4 bb  = ((const float4*)b2)[c16 * 2 + 1];

        float4 oa, ob;
        oa.x = acc[0] + u2v * c1a.x + u1v * c2a.x + ba.x;
        oa.y = acc[1] + u2v * c1a.y + u1v * c2a.y + ba.y;
        oa.z = acc[2] + u2v * c1a.z + u1v * c2a.z + ba.z;
        oa.w = acc[3] + u2v * c1a.w + u1v * c2a.w + ba.w;
        ob.x = acc[4] + u2v * c1b.x + u1v * c2b.x + bb.x;
        ob.y = acc[5] + u2v * c1b.y + u1v * c2b.y + bb.y;
        ob.z = acc[6] + u2v * c1b.z + u1v * c2b.z + bb.z;
        ob.w = acc[7] + u2v * c1b.w + u1v * c2b.w + bb.w;
        ((float4*)out)[(size_t)warp * 32 + c16 * 2]     = oa;
        ((float4*)out)[(size_t)warp * 32 + c16 * 2 + 1] = ob;
    }
}

// ---------------- launch: fork preproc onto side stream, overlap with GEMM branch ----------------
extern "C" void kernel_launch(void* const* d_in, const int* in_sizes, int n_in,
                              void* d_out, int out_size) {
    const float* feat = (const float*)d_in[0];
    const int*   ei   = (const int*)d_in[1];
    const float* W0 = (const float*)d_in[2];
    const float* b0 = (const float*)d_in[3];
    const float* W1 = (const float*)d_in[4];
    const float* b1 = (const float*)d_in[5];
    const float* W2 = (const float*)d_in[6];
    const float* b2 = (const float*)d_in[7];

    int n = in_sizes[0] / D;
    int e = in_sizes[1] / 2;
    if (n > NMAX) n = NMAX;
    if (e > EMAX) e = EMAX;
    const int* src = ei;
    const int* dstp = ei + e;

    __half *Hp, *Ap;
    float *Wtp, *W012p;
    cudaGetSymbolAddress((void**)&Hp, g_H);
    cudaGetSymbolAddress((void**)&Ap, g_A);
    cudaGetSymbolAddress((void**)&Wtp, g_Wt);
    cudaGetSymbolAddress((void**)&W012p, g_W012);

    // one-time side stream + events (created on first, non-captured, call)
    static cudaStream_t s_side = nullptr;
    static cudaEvent_t  s_fork = nullptr, s_join = nullptr;
    if (!s_side) {
        cudaStreamCreateWithFlags(&s_side, cudaStreamNonBlocking);
        cudaEventCreateWithFlags(&s_fork, cudaEventDisableTiming);
        cudaEventCreateWithFlags(&s_join, cudaEventDisableTiming);
    }

    int nb = (n + 1023) / 1024;
    int gm = (n + 127) / 128;
    int ga = (int)(((long long)n * 32 + 255) / 256);
    int gn = (n + 255) / 256;

    // fork: CSR build + scalar aggregations on side stream
    cudaEventRecord(s_fork, 0);
    cudaStreamWaitEvent(s_side, s_fork, 0);
    k_zero<<<gn, 256, 0, s_side>>>(n);
    k_count<<<(e + 255) / 256, 256, 0, s_side>>>(dstp, e);
    k_scan1<<<nb, 1024, 0, s_side>>>(n);
    k_scan3<<<nb, 1024, 0, s_side>>>(n, e);
    k_scatter<<<(e + 255) / 256, 256, 0, s_side>>>(src, dstp, e);
    k_aggs1<<<gn, 256, 0, s_side>>>(n);
    k_aggs2<<<gn, 256, 0, s_side>>>(n);
    cudaEventRecord(s_join, s_side);

    // main: collapsed weights + GEMM (independent of graph preprocessing)
    k_mm128<<<64, 256>>>(W0, W1, Wtp);
    k_mm128<<<64, 256>>>(Wtp, W2, W012p);
    k_cvec<<<1, 128>>>(b0, b1, W1, W2);
    k_gemm<<<gm, 256>>>(feat, W012p, Hp, n);

    // join: aggregations need both CSR and Y
    cudaStreamWaitEvent(0, s_join, 0);
    k_agg_mid<<<ga, 256>>>(Hp, Ap, n);
    k_agg_mid<<<ga, 256>>>(Ap, Hp, n);
    k_agg_fin<<<ga, 256>>>(Hp, b2, (float*)d_out, n);
}

// round 12
// speedup vs baseline: 1.0563x; 1.0563x over previous
#include <cuda_runtime.h>
#include <cuda_fp16.h>
#include <cstdint>
#include <cstddef>

#define NMAX 100000
#define EMAX 1600000
#define D 128

// ---------------- static device scratch ----------------
__device__ __half g_H[(size_t)NMAX * D];    // ping buffer, fp16 (pre-scaled G)
__device__ __half g_A[(size_t)NMAX * D];    // pong buffer, fp16
__device__ int    g_cnt[NMAX];
__device__ float  g_dis[NMAX];
__device__ int    g_rs[NMAX + 1];
__device__ int    g_cur[NMAX];
__device__ int    g_bsum[256];
__device__ int    g_csrs[EMAX];
__device__ float  g_Wt[128 * 128];          // W0*W1
__device__ float  g_W012[128 * 128];        // W0*W1*W2
__device__ float  g_c1[128];                // b0*W1*W2
__device__ float  g_c2[128];                // b1*W2
__device__ float  g_u1[NMAX];               // A*1
__device__ float  g_t1[NMAX];               // dis * u1
__device__ float  g_u2[NMAX];               // A^2*1

// ---------------- graph preprocessing ----------------
__global__ void k_zero(int n) {
    int i = blockIdx.x * blockDim.x + threadIdx.x;
    if (i < n) g_cnt[i] = 0;
}

__global__ void k_count(const int* __restrict__ dst, int e) {
    int i = blockIdx.x * blockDim.x + threadIdx.x;
    if (i < e) atomicAdd(&g_cnt[dst[i]], 1);
}

__global__ void k_scan1(int n) {
    __shared__ int sm[1024];
    int i = blockIdx.x * 1024 + threadIdx.x;
    int v = (i < n) ? g_cnt[i] : 0;
    sm[threadIdx.x] = v;
    __syncthreads();
    for (int off = 1; off < 1024; off <<= 1) {
        int t = (threadIdx.x >= (unsigned)off) ? sm[threadIdx.x - off] : 0;
        __syncthreads();
        sm[threadIdx.x] += t;
        __syncthreads();
    }
    if (i < n) g_rs[i] = sm[threadIdx.x] - v;   // exclusive within block
    if (threadIdx.x == 1023) g_bsum[blockIdx.x] = sm[1023];
}

__global__ void k_scan3(int n, int e) {
    __shared__ int red[128];
    int b = blockIdx.x;
    int t = threadIdx.x;
    if (t < 128) red[t] = (t < b) ? g_bsum[t] : 0;
    __syncthreads();
    for (int off = 64; off > 0; off >>= 1) {
        if (t < (unsigned)off) red[t] += red[t + off];
        __syncthreads();
    }
    int pre = red[0];
    int i = b * 1024 + t;
    if (i < n) {
        int v = g_rs[i] + pre;
        g_rs[i] = v;
        g_cur[i] = v;
        g_dis[i] = rsqrtf((float)(g_cnt[i] + 1));   // +1 self loop
    }
    if (i == 0) g_rs[n] = e;
}

// index-only scatter (weights eliminated algebraically)
__global__ void k_scatter(const int* __restrict__ src, const int* __restrict__ dst, int e) {
    int i = blockIdx.x * blockDim.x + threadIdx.x;
    if (i < e) {
        int d = dst[i];
        int p = atomicAdd(&g_cur[d], 1);
        g_csrs[p] = src[i];
    }
}

// ---------------- tiny fp32 matmul: C[128x128] = A*B ----------------
__global__ void k_mm128(const float* __restrict__ A, const float* __restrict__ B,
                        float* __restrict__ C) {
    int id = blockIdx.x * 256 + threadIdx.x;
    int r = id >> 7, c = id & 127;
    float s = 0.0f;
#pragma unroll 8
    for (int k = 0; k < 128; k++) s = fmaf(A[r * 128 + k], B[k * 128 + c], s);
    C[id] = s;
}

// ---------------- bias correction vectors: c1 = b0*W1*W2, c2 = b1*W2 ----------------
__global__ void k_cvec(const float* __restrict__ b0, const float* __restrict__ b1,
                       const float* __restrict__ W1, const float* __restrict__ W2) {
    __shared__ float t1[128];
    int j = threadIdx.x;
    float s = 0.0f;
    for (int k = 0; k < 128; k++) s = fmaf(b0[k], W1[k * 128 + j], s);
    t1[j] = s;
    __syncthreads();
    float s1 = 0.0f, s2 = 0.0f;
    for (int k = 0; k < 128; k++) {
        float w = W2[k * 128 + j];
        s1 = fmaf(t1[k], w, s1);
        s2 = fmaf(b1[k], w, s2);
    }
    g_c1[j] = s1;
    g_c2[j] = s2;
}

// ---------------- scalar aggregations: u1 = A*1, u2 = A*u1 (weight-free form) ----------------
__global__ void k_aggs1(int n) {
    int v = blockIdx.x * blockDim.x + threadIdx.x;
    if (v >= n) return;
    float dv = g_dis[v];
    float s = dv;                               // self: G=dis
    int end = g_rs[v + 1];
    for (int e = g_rs[v]; e < end; e++) s += g_dis[g_csrs[e]];
    float u1 = dv * s;
    g_u1[v] = u1;
    g_t1[v] = dv * u1;
}

__global__ void k_aggs2(int n) {
    int v = blockIdx.x * blockDim.x + threadIdx.x;
    if (v >= n) return;
    float dv = g_dis[v];
    float s = g_t1[v];                          // self: dis*u1
    int end = g_rs[v + 1];
    for (int e = g_rs[v]; e < end; e++) s += g_t1[g_csrs[e]];
    g_u2[v] = dv * s;
}

// ---------------- MMA helpers ----------------
__device__ __forceinline__ void mma_f16(float* c, const unsigned* a, unsigned b0, unsigned b1) {
    asm volatile(
        "mma.sync.aligned.m16n8k16.row.col.f32.f16.f16.f32 "
        "{%0,%1,%2,%3}, {%4,%5,%6,%7}, {%8,%9}, {%0,%1,%2,%3};\n"
        : "+f"(c[0]), "+f"(c[1]), "+f"(c[2]), "+f"(c[3])
        : "r"(a[0]), "r"(a[1]), "r"(a[2]), "r"(a[3]), "r"(b0), "r"(b1));
}

#define BSTR 136   // smem stride in uint32 -> conflict-free frag loads

// ---------------- GEMM: G0 = diag(dis) * (X @ W012), fp16 out ----------------
__global__ void __launch_bounds__(256)
k_gemm(const float* __restrict__ X, const float* __restrict__ W,
       __half* __restrict__ H, int n) {
    __shared__ unsigned Bh[64 * BSTR];

    int tid = threadIdx.x;
    for (int i = tid; i < 64 * 128; i += 256) {
        int j = i >> 7, c = i & 127;
        float w0 = W[(2 * j) * 128 + c];
        float w1 = W[(2 * j + 1) * 128 + c];
        __half2 h = __floats2half2_rn(w0, w1);
        Bh[j * BSTR + c] = *(unsigned*)&h;
    }
    __syncthreads();

    int wid = tid >> 5, lane = tid & 31;
    int warp_m = wid >> 1, warp_n = wid & 1;
    int g = lane >> 2, tg = lane & 3;
    int rbase = blockIdx.x * 128 + warp_m * 32;
    int cbase = warp_n * 64;
    int nclamp = n - 1;

    float acc[2][8][4];
#pragma unroll
    for (int mf = 0; mf < 2; mf++)
#pragma unroll
        for (int nt = 0; nt < 8; nt++)
#pragma unroll
            for (int q = 0; q < 4; q++) acc[mf][nt][q] = 0.0f;

    for (int k0 = 0; k0 < 128; k0 += 16) {
        unsigned a[2][4];
#pragma unroll
        for (int mf = 0; mf < 2; mf++) {
            int r0 = rbase + mf * 16 + g;
            int r1 = r0 + 8;
            if (r0 > nclamp) r0 = nclamp;
            if (r1 > nclamp) r1 = nclamp;
            const float* p0 = X + (size_t)r0 * D + k0 + 2 * tg;
            const float* p1 = X + (size_t)r1 * D + k0 + 2 * tg;
            float2 f00 = *(const float2*)(p0);
            float2 f01 = *(const float2*)(p0 + 8);
            float2 f10 = *(const float2*)(p1);
            float2 f11 = *(const float2*)(p1 + 8);
            __half2 h0 = __floats2half2_rn(f00.x, f00.y);
            __half2 h1 = __floats2half2_rn(f10.x, f10.y);
            __half2 h2 = __floats2half2_rn(f01.x, f01.y);
            __half2 h3 = __floats2half2_rn(f11.x, f11.y);
            a[mf][0] = *(unsigned*)&h0;
            a[mf][1] = *(unsigned*)&h1;
            a[mf][2] = *(unsigned*)&h2;
            a[mf][3] = *(unsigned*)&h3;
        }
#pragma unroll
        for (int nt = 0; nt < 8; nt++) {
            int c = cbase + nt * 8 + g;
            int i0 = (k0 / 2 + tg) * BSTR + c;
            int i1 = i0 + 4 * BSTR;
            unsigned b0 = Bh[i0], b1 = Bh[i1];
#pragma unroll
            for (int mf = 0; mf < 2; mf++)
                mma_f16(acc[mf][nt], a[mf], b0, b1);
        }
    }

#pragma unroll
    for (int mf = 0; mf < 2; mf++) {
        int r0 = rbase + mf * 16 + g;
        int r1 = r0 + 8;
        float d0 = (r0 < n) ? g_dis[r0] : 0.0f;
        float d1 = (r1 < n) ? g_dis[r1] : 0.0f;
#pragma unroll
        for (int nt = 0; nt < 8; nt++) {
            int c = cbase + nt * 8 + 2 * tg;
            if (r0 < n) {
                __half2 v = __floats2half2_rn(d0 * acc[mf][nt][0], d0 * acc[mf][nt][1]);
                *(__half2*)(H + (size_t)r0 * D + c) = v;
            }
            if (r1 < n) {
                __half2 v = __floats2half2_rn(d1 * acc[mf][nt][2], d1 * acc[mf][nt][3]);
                *(__half2*)(H + (size_t)r1 * D + c) = v;
            }
        }
    }
}

// ---------------- aggregation v3: weight-free sum of pre-scaled rows ----------------
// lane = half*16 + c16; each lane owns 8 columns.
// half 0: even edges + self row; half 1: odd edges. shfl_xor(16) merge.
__device__ __forceinline__ void unpack_add8(float* acc, uint4 u) {
    float2 p0 = __half22float2(*(__half2*)&u.x);
    float2 p1 = __half22float2(*(__half2*)&u.y);
    float2 p2 = __half22float2(*(__half2*)&u.z);
    float2 p3 = __half22float2(*(__half2*)&u.w);
    acc[0] += p0.x; acc[1] += p0.y;
    acc[2] += p1.x; acc[3] += p1.y;
    acc[4] += p2.x; acc[5] += p2.y;
    acc[6] += p3.x; acc[7] += p3.y;
}

__device__ __forceinline__ void agg_sum(const uint4* __restrict__ H4, int node,
                                        int half, int c16, float* acc) {
#pragma unroll
    for (int i = 0; i < 8; i++) acc[i] = 0.0f;

    // self row (half 0 only)
    if (half == 0) {
        uint4 uv = H4[(size_t)node * 16 + c16];
        unpack_add8(acc, uv);
    }

    int e = g_rs[node], end = g_rs[node + 1];
    for (; e + 8 <= end; e += 8) {
        int i0 = e + half, i1 = e + 2 + half, i2 = e + 4 + half, i3 = e + 6 + half;
        int s0 = g_csrs[i0], s1 = g_csrs[i1], s2 = g_csrs[i2], s3 = g_csrs[i3];
        uint4 u0 = H4[(size_t)s0 * 16 + c16];
        uint4 u1 = H4[(size_t)s1 * 16 + c16];
        uint4 u2 = H4[(size_t)s2 * 16 + c16];
        uint4 u3 = H4[(size_t)s3 * 16 + c16];
        unpack_add8(acc, u0);
        unpack_add8(acc, u1);
        unpack_add8(acc, u2);
        unpack_add8(acc, u3);
    }
    for (; e < end; e += 2) {
        int idx = e + half;
        if (idx < end) {
            uint4 u = H4[(size_t)g_csrs[idx] * 16 + c16];
            unpack_add8(acc, u);
        }
    }
#pragma unroll
    for (int i = 0; i < 8; i++)
        acc[i] += __shfl_xor_sync(0xffffffffu, acc[i], 16);
}

// mid aggregation: writes dis^2 * S (pre-scaled for next pass), fp16
__global__ void k_agg_mid(const __half* __restrict__ Hh, __half* __restrict__ Oh, int n) {
    int warp = (blockIdx.x * blockDim.x + threadIdx.x) >> 5;
    int lane = threadIdx.x & 31;
    if (warp >= n) return;
    int half = lane >> 4, c16 = lane & 15;

    float acc[8];
    agg_sum((const uint4*)Hh, warp, half, c16, acc);

    if (half == 0) {
        float dv = g_dis[warp];
        float s2 = dv * dv;
        __half2 h0 = __floats2half2_rn(s2 * acc[0], s2 * acc[1]);
        __half2 h1 = __floats2half2_rn(s2 * acc[2], s2 * acc[3]);
        __half2 h2 = __floats2half2_rn(s2 * acc[4], s2 * acc[5]);
        __half2 h3 = __floats2half2_rn(s2 * acc[6], s2 * acc[7]);
        uint4 o;
        o.x = *(unsigned*)&h0;
        o.y = *(unsigned*)&h1;
        o.z = *(unsigned*)&h2;
        o.w = *(unsigned*)&h3;
        ((uint4*)Oh)[(size_t)warp * 16 + c16] = o;
    }
}

// final aggregation: dis * S + rank-1 bias corrections + b2, fp32 out
__global__ void k_agg_fin(const __half* __restrict__ Hh, const float* __restrict__ b2,
                          float* __restrict__ out, int n) {
    int warp = (blockIdx.x * blockDim.x + threadIdx.x) >> 5;
    int lane = threadIdx.x & 31;
    if (warp >= n) return;
    int half = lane >> 4, c16 = lane & 15;

    float acc[8];
    agg_sum((const uint4*)Hh, warp, half, c16, acc);

    if (half == 0) {
        float dv  = g_dis[warp];
        float u2v = g_u2[warp];
        float u1v = g_u1[warp];
        float4 c1a = ((const float4*)g_c1)[c16 * 2];
        float4 c1b = ((const float4*)g_c1)[c16 * 2 + 1];
        float4 c2a = ((const float4*)g_c2)[c16 * 2];
        float4 c2b = ((const float4*)g_c2)[c16 * 2 + 1];
        float4 ba  = ((const float4*)b2)[c16 * 2];
        float4 bb  = ((const float4*)b2)[c16 * 2 + 1];

        float4 oa, ob;
        oa.x = dv * acc[0] + u2v * c1a.x + u1v * c2a.x + ba.x;
        oa.y = dv * acc[1] + u2v * c1a.y + u1v * c2a.y + ba.y;
        oa.z = dv * acc[2] + u2v * c1a.z + u1v * c2a.z + ba.z;
        oa.w = dv * acc[3] + u2v * c1a.w + u1v * c2a.w + ba.w;
        ob.x = dv * acc[4] + u2v * c1b.x + u1v * c2b.x + bb.x;
        ob.y = dv * acc[5] + u2v * c1b.y + u1v * c2b.y + bb.y;
        ob.z = dv * acc[6] + u2v * c1b.z + u1v * c2b.z + bb.z;
        ob.w = dv * acc[7] + u2v * c1b.w + u1v * c2b.w + bb.w;
        ((float4*)out)[(size_t)warp * 32 + c16 * 2]     = oa;
        ((float4*)out)[(size_t)warp * 32 + c16 * 2 + 1] = ob;
    }
}

// ---------------- launch ----------------
extern "C" void kernel_launch(void* const* d_in, const int* in_sizes, int n_in,
                              void* d_out, int out_size) {
    const float* feat = (const float*)d_in[0];
    const int*   ei   = (const int*)d_in[1];
    const float* W0 = (const float*)d_in[2];
    const float* b0 = (const float*)d_in[3];
    const float* W1 = (const float*)d_in[4];
    const float* b1 = (const float*)d_in[5];
    const float* W2 = (const float*)d_in[6];
    const float* b2 = (const float*)d_in[7];

    int n = in_sizes[0] / D;
    int e = in_sizes[1] / 2;
    if (n > NMAX) n = NMAX;
    if (e > EMAX) e = EMAX;
    const int* src = ei;
    const int* dstp = ei + e;

    __half *Hp, *Ap;
    float *Wtp, *W012p;
    cudaGetSymbolAddress((void**)&Hp, g_H);
    cudaGetSymbolAddress((void**)&Ap, g_A);
    cudaGetSymbolAddress((void**)&Wtp, g_Wt);
    cudaGetSymbolAddress((void**)&W012p, g_W012);

    static cudaStream_t s_side = nullptr;
    static cudaEvent_t  s_fork = nullptr, s_dis = nullptr, s_join = nullptr;
    if (!s_side) {
        cudaStreamCreateWithFlags(&s_side, cudaStreamNonBlocking);
        cudaEventCreateWithFlags(&s_fork, cudaEventDisableTiming);
        cudaEventCreateWithFlags(&s_dis, cudaEventDisableTiming);
        cudaEventCreateWithFlags(&s_join, cudaEventDisableTiming);
    }

    int nb = (n + 1023) / 1024;
    int gm = (n + 127) / 128;
    int ga = (int)(((long long)n * 32 + 255) / 256);
    int gn = (n + 255) / 256;

    // fork: CSR build + scalar aggregations on side stream
    cudaEventRecord(s_fork, 0);
    cudaStreamWaitEvent(s_side, s_fork, 0);
    k_zero<<<gn, 256, 0, s_side>>>(n);
    k_count<<<(e + 255) / 256, 256, 0, s_side>>>(dstp, e);
    k_scan1<<<nb, 1024, 0, s_side>>>(n);
    k_scan3<<<nb, 1024, 0, s_side>>>(n, e);
    cudaEventRecord(s_dis, s_side);                     // dis + rowstarts ready
    k_scatter<<<(e + 255) / 256, 256, 0, s_side>>>(src, dstp, e);
    k_aggs1<<<gn, 256, 0, s_side>>>(n);
    k_aggs2<<<gn, 256, 0, s_side>>>(n);
    cudaEventRecord(s_join, s_side);

    // main: collapsed weights run during preproc; gemm waits only for dis
    k_mm128<<<64, 256>>>(W0, W1, Wtp);
    k_mm128<<<64, 256>>>(Wtp, W2, W012p);
    k_cvec<<<1, 128>>>(b0, b1, W1, W2);
    cudaStreamWaitEvent(0, s_dis, 0);
    k_gemm<<<gm, 256>>>(feat, W012p, Hp, n);

    // join: aggregations need CSR + scalar sums + G0
    cudaStreamWaitEvent(0, s_join, 0);
    k_agg_mid<<<ga, 256>>>(Hp, Ap, n);
    k_agg_mid<<<ga, 256>>>(Ap, Hp, n);
    k_agg_fin<<<ga, 256>>>(Hp, b2, (float*)d_out, n);
}